// round 5
// baseline (speedup 1.0000x reference)
#include <cuda_runtime.h>
#include <math.h>

#define DIM 768
#define NEXP 8
#define VEC (DIM / 4)          // 192 float4 per token row
#define V_PER_LANE (VEC / 32)  // 6 float4 chunks per lane
#define THREADS 256
#define WARPS_PER_BLOCK (THREADS / 32)
#define TOK_PER_WARP 4
#define TOK_PER_BLOCK (WARPS_PER_BLOCK * TOK_PER_WARP)  // 32

__global__ __launch_bounds__(THREADS)
void router_kernel(const float* __restrict__ x,
                   const float* __restrict__ W,
                   const float* __restrict__ b,
                   float* __restrict__ out,
                   int ntok,
                   int write_idx) {
    // Stage W [8,768] = 24 KB into shared (coalesced float4) + bias.
    __shared__ float4 sW[NEXP * VEC];
    __shared__ float sB[NEXP];
    const float4* Wv = reinterpret_cast<const float4*>(W);
    for (int i = threadIdx.x; i < NEXP * VEC; i += THREADS) sW[i] = Wv[i];
    if (threadIdx.x < NEXP) sB[threadIdx.x] = b[threadIdx.x];
    __syncthreads();

    const int lane = threadIdx.x & 31;
    const int warp = threadIdx.x >> 5;
    const int tok0 = (blockIdx.x * WARPS_PER_BLOCK + warp) * TOK_PER_WARP;
    if (tok0 >= ntok) return;

    float acc[TOK_PER_WARP][NEXP];
#pragma unroll
    for (int t = 0; t < TOK_PER_WARP; t++)
#pragma unroll
        for (int e = 0; e < NEXP; e++) acc[t][e] = 0.0f;

    const float4* xv = reinterpret_cast<const float4*>(x);

    // Per chunk: 4 LDG.128 (x, one per token) + 8 LDS.128 (W) + 128 FFMA.
    // Each W fragment is reused across 4 tokens -> smem traffic 6 KB/token.
#pragma unroll
    for (int k = 0; k < V_PER_LANE; k++) {
        float4 xa[TOK_PER_WARP];
#pragma unroll
        for (int t = 0; t < TOK_PER_WARP; t++) {
            int tok = tok0 + t;
            if (tok >= ntok) tok = ntok - 1;  // safe redundant read on tail
            xa[t] = xv[(size_t)tok * VEC + lane + 32 * k];
        }
#pragma unroll
        for (int e = 0; e < NEXP; e++) {
            const float4 w = sW[e * VEC + lane + 32 * k];
#pragma unroll
            for (int t = 0; t < TOK_PER_WARP; t++) {
                acc[t][e] += xa[t].x * w.x + xa[t].y * w.y +
                             xa[t].z * w.z + xa[t].w * w.w;
            }
        }
    }

    // Butterfly-reduce all 32 accumulators across the warp; every lane ends
    // with the full sums.
#pragma unroll
    for (int off = 16; off > 0; off >>= 1) {
#pragma unroll
        for (int t = 0; t < TOK_PER_WARP; t++)
#pragma unroll
            for (int e = 0; e < NEXP; e++)
                acc[t][e] += __shfl_xor_sync(0xffffffffu, acc[t][e], off);
    }

    // Lanes 0..3 each finish one token: bias + softmax + top-2.
    if (lane < TOK_PER_WARP) {
        const int token = tok0 + lane;
        if (token < ntok) {
            float logits[NEXP];
            float m = -INFINITY;
#pragma unroll
            for (int e = 0; e < NEXP; e++) {
                logits[e] = acc[lane][e] + sB[e];
                m = fmaxf(m, logits[e]);
            }
            float s = 0.0f;
            float ex[NEXP];
#pragma unroll
            for (int e = 0; e < NEXP; e++) {
                ex[e] = __expf(logits[e] - m);
                s += ex[e];
            }
            const float inv_s = 1.0f / s;

            // top-2 by logit (softmax monotonic); strict > keeps lowest index
            // on ties, matching jax.lax.top_k.
            int i0 = 0;
#pragma unroll
            for (int e = 1; e < NEXP; e++)
                if (logits[e] > logits[i0]) i0 = e;
            int i1 = (i0 == 0) ? 1 : 0;
#pragma unroll
            for (int e = 0; e < NEXP; e++)
                if (e != i0 && logits[e] > logits[i1]) i1 = e;

            // Output layout: [gates (ntok*2 f32)] ++ [indices (ntok*2 as f32)]
            out[token * 2 + 0] = ex[i0] * inv_s;
            out[token * 2 + 1] = ex[i1] * inv_s;
            if (write_idx) {
                float* oi = out + (size_t)ntok * 2;
                oi[token * 2 + 0] = (float)i0;
                oi[token * 2 + 1] = (float)i1;
            }
        }
    }
}

extern "C" void kernel_launch(void* const* d_in, const int* in_sizes, int n_in,
                              void* d_out, int out_size) {
    const float* x = (const float*)d_in[0];
    const float* W = (const float*)d_in[1];
    const float* b = (const float*)d_in[2];
    float* out = (float*)d_out;

    const int ntok = in_sizes[0] / DIM;                 // 128*197 = 25216
    const int write_idx = (out_size >= 4 * ntok) ? 1 : 0;

    const int grid = (ntok + TOK_PER_BLOCK - 1) / TOK_PER_BLOCK;
    router_kernel<<<grid, THREADS>>>(x, W, b, out, ntok, write_idx);
}

// round 11
// speedup vs baseline: 1.0083x; 1.0083x over previous
#include <cuda_runtime.h>
#include <math.h>

#define DIM 768
#define NEXP 8
#define VEC (DIM / 4)            // 192 float4 per token row
#define HLANES 16                // lanes per half-warp
#define CHUNKS (VEC / HLANES)    // 12 float4 chunks per lane (half-warp covers row)
#define EXP_HALF (NEXP / 2)      // 4 experts per half-warp
#define THREADS 256
#define WARPS_PER_BLOCK (THREADS / 32)
#define TOK_PER_WARP 4
#define TOK_PER_BLOCK (WARPS_PER_BLOCK * TOK_PER_WARP)  // 32

__global__ __launch_bounds__(THREADS, 4)
void router_kernel(const float* __restrict__ x,
                   const float* __restrict__ W,
                   const float* __restrict__ b,
                   float* __restrict__ out,
                   int ntok,
                   int write_idx) {
    // Stage W [8,768] = 24 KB into shared (coalesced float4) + bias.
    __shared__ float4 sW[NEXP * VEC];
    __shared__ float sB[NEXP];
    __shared__ float sLog[WARPS_PER_BLOCK][TOK_PER_WARP][NEXP];  // half-warp exchange
    const float4* Wv = reinterpret_cast<const float4*>(W);
    for (int i = threadIdx.x; i < NEXP * VEC; i += THREADS) sW[i] = Wv[i];
    if (threadIdx.x < NEXP) sB[threadIdx.x] = b[threadIdx.x];
    __syncthreads();

    const int lane = threadIdx.x & 31;
    const int warp = threadIdx.x >> 5;
    const int half = lane >> 4;       // 0: experts 0-3, 1: experts 4-7
    const int hl   = lane & 15;       // lane within half-warp
    const int eBase = half * EXP_HALF;
    const int tok0 = (blockIdx.x * WARPS_PER_BLOCK + warp) * TOK_PER_WARP;
    if (tok0 >= ntok) return;

    // Clamp tail tokens (redundant read + discarded result; exact grid has no tail).
    int tok[TOK_PER_WARP];
#pragma unroll
    for (int t = 0; t < TOK_PER_WARP; t++) {
        int tt = tok0 + t;
        tok[t] = (tt < ntok) ? tt : (ntok - 1);
    }

    float acc[TOK_PER_WARP][EXP_HALF];
#pragma unroll
    for (int t = 0; t < TOK_PER_WARP; t++)
#pragma unroll
        for (int e = 0; e < EXP_HALF; e++) acc[t][e] = 0.0f;

    const float4* xv = reinterpret_cast<const float4*>(x);

    // Per chunk: 4 x-LDG.128 (both halves read identical addresses -> dedup'd
    // wavefronts) + 4 W-LDS.128 (distinct per half) + 64 FFMA.
#pragma unroll 2
    for (int k = 0; k < CHUNKS; k++) {
        const int idx = hl + HLANES * k;
        float4 xa[TOK_PER_WARP];
#pragma unroll
        for (int t = 0; t < TOK_PER_WARP; t++)
            xa[t] = xv[(size_t)tok[t] * VEC + idx];
#pragma unroll
        for (int e = 0; e < EXP_HALF; e++) {
            const float4 w = sW[(eBase + e) * VEC + idx];
#pragma unroll
            for (int t = 0; t < TOK_PER_WARP; t++) {
                acc[t][e] += xa[t].x * w.x + xa[t].y * w.y +
                             xa[t].z * w.z + xa[t].w * w.w;
            }
        }
    }

    // Butterfly reduce within each half-warp (offsets 8..1 stay in-half).
#pragma unroll
    for (int off = 8; off > 0; off >>= 1) {
#pragma unroll
        for (int t = 0; t < TOK_PER_WARP; t++)
#pragma unroll
            for (int e = 0; e < EXP_HALF; e++)
                acc[t][e] += __shfl_xor_sync(0xffffffffu, acc[t][e], off);
    }

    // Exchange halves via smem: lane hl<4 of each half publishes token hl's
    // 4 expert sums.
    if (hl < TOK_PER_WARP) {
#pragma unroll
        for (int e = 0; e < EXP_HALF; e++)
            sLog[warp][hl][eBase + e] = acc[hl][e];
    }
    __syncwarp();

    // Lanes 0..3 each finish one token: bias + softmax + top-2.
    if (lane < TOK_PER_WARP) {
        const int token = tok0 + lane;
        if (token < ntok) {
            float logits[NEXP];
            float m = -INFINITY;
#pragma unroll
            for (int e = 0; e < NEXP; e++) {
                logits[e] = sLog[warp][lane][e] + sB[e];
                m = fmaxf(m, logits[e]);
            }
            float s = 0.0f;
            float ex[NEXP];
#pragma unroll
            for (int e = 0; e < NEXP; e++) {
                ex[e] = __expf(logits[e] - m);
                s += ex[e];
            }
            const float inv_s = 1.0f / s;

            // top-2 by logit (softmax monotonic); strict > keeps lowest index
            // on ties, matching jax.lax.top_k.
            int i0 = 0;
#pragma unroll
            for (int e = 1; e < NEXP; e++)
                if (logits[e] > logits[i0]) i0 = e;
            int i1 = (i0 == 0) ? 1 : 0;
#pragma unroll
            for (int e = 0; e < NEXP; e++)
                if (e != i0 && logits[e] > logits[i1]) i1 = e;

            // Output layout: [gates (ntok*2 f32)] ++ [indices (ntok*2 as f32)]
            out[token * 2 + 0] = ex[i0] * inv_s;
            out[token * 2 + 1] = ex[i1] * inv_s;
            if (write_idx) {
                float* oi = out + (size_t)ntok * 2;
                oi[token * 2 + 0] = (float)i0;
                oi[token * 2 + 1] = (float)i1;
            }
        }
    }
}

extern "C" void kernel_launch(void* const* d_in, const int* in_sizes, int n_in,
                              void* d_out, int out_size) {
    const float* x = (const float*)d_in[0];
    const float* W = (const float*)d_in[1];
    const float* b = (const float*)d_in[2];
    float* out = (float*)d_out;

    const int ntok = in_sizes[0] / DIM;                 // 128*197 = 25216
    const int write_idx = (out_size >= 4 * ntok) ? 1 : 0;

    const int grid = (ntok + TOK_PER_BLOCK - 1) / TOK_PER_BLOCK;
    router_kernel<<<grid, THREADS>>>(x, W, b, out, ntok, write_idx);
}

// round 13
// speedup vs baseline: 1.1089x; 1.0999x over previous
#include <cuda_runtime.h>
#include <math.h>

#define DIM 768
#define NEXP 8
#define VEC (DIM / 4)            // 192 float4 per token row
#define HLANES 16                // lanes per half-warp
#define CHUNKS (VEC / HLANES)    // 12 float4 chunks per lane (half-warp covers row)
#define EXP_HALF (NEXP / 2)      // 4 experts per half-warp
#define THREADS 256
#define WARPS_PER_BLOCK (THREADS / 32)
#define TOK_PER_WARP 4
#define TOK_PER_BLOCK (WARPS_PER_BLOCK * TOK_PER_WARP)  // 32
#define NBLOCKS 444              // 148 SMs * 3 blocks/SM -> single persistent wave

__global__ __launch_bounds__(THREADS, 3)
void router_kernel(const float* __restrict__ x,
                   const float* __restrict__ W,
                   const float* __restrict__ b,
                   float* __restrict__ out,
                   int ntok,
                   int write_idx) {
    // Stage W [8,768] = 24 KB into shared (coalesced float4) + bias.
    __shared__ float4 sW[NEXP * VEC];
    __shared__ float sB[NEXP];
    __shared__ float sLog[WARPS_PER_BLOCK][TOK_PER_WARP][NEXP];  // half-warp exchange
    const float4* Wv = reinterpret_cast<const float4*>(W);
    for (int i = threadIdx.x; i < NEXP * VEC; i += THREADS) sW[i] = Wv[i];
    if (threadIdx.x < NEXP) sB[threadIdx.x] = b[threadIdx.x];
    __syncthreads();

    const int lane = threadIdx.x & 31;
    const int warp = threadIdx.x >> 5;
    const int half = lane >> 4;       // 0: experts 0-3, 1: experts 4-7
    const int hl   = lane & 15;       // lane within half-warp
    const int eBase = half * EXP_HALF;
    const float4* xv = reinterpret_cast<const float4*>(x);
    const int ntiles = (ntok + TOK_PER_BLOCK - 1) / TOK_PER_BLOCK;

    // Persistent grid-stride over token tiles (one wave, no quantization tail).
    for (int tile = blockIdx.x; tile < ntiles; tile += NBLOCKS) {
        const int tok0 = tile * TOK_PER_BLOCK + warp * TOK_PER_WARP;

        // Clamped per-token row pointers (tail reads are redundant, discarded).
        const float4* xp[TOK_PER_WARP];
#pragma unroll
        for (int t = 0; t < TOK_PER_WARP; t++) {
            int tt = tok0 + t;
            if (tt >= ntok) tt = ntok - 1;
            xp[t] = xv + (size_t)tt * VEC + hl;
        }

        float acc[TOK_PER_WARP][EXP_HALF];
#pragma unroll
        for (int t = 0; t < TOK_PER_WARP; t++)
#pragma unroll
            for (int e = 0; e < EXP_HALF; e++) acc[t][e] = 0.0f;

        // Software-pipelined mainloop: prefetch chunk k+1's x while doing
        // chunk k's FMAs, so the ~DRAM latency overlaps compute in-warp.
        float4 xa[TOK_PER_WARP], xb[TOK_PER_WARP];
#pragma unroll
        for (int t = 0; t < TOK_PER_WARP; t++) xa[t] = xp[t][0];

#pragma unroll
        for (int k = 0; k < CHUNKS; k++) {
            if (k + 1 < CHUNKS) {
#pragma unroll
                for (int t = 0; t < TOK_PER_WARP; t++)
                    xb[t] = xp[t][HLANES * (k + 1)];
            }
#pragma unroll
            for (int e = 0; e < EXP_HALF; e++) {
                const float4 w = sW[(eBase + e) * VEC + hl + HLANES * k];
#pragma unroll
                for (int t = 0; t < TOK_PER_WARP; t++) {
                    acc[t][e] += xa[t].x * w.x + xa[t].y * w.y +
                                 xa[t].z * w.z + xa[t].w * w.w;
                }
            }
            if (k + 1 < CHUNKS) {
#pragma unroll
                for (int t = 0; t < TOK_PER_WARP; t++) xa[t] = xb[t];
            }
        }

        // Butterfly reduce within each half-warp (offsets 8..1 stay in-half).
#pragma unroll
        for (int off = 8; off > 0; off >>= 1) {
#pragma unroll
            for (int t = 0; t < TOK_PER_WARP; t++)
#pragma unroll
                for (int e = 0; e < EXP_HALF; e++)
                    acc[t][e] += __shfl_xor_sync(0xffffffffu, acc[t][e], off);
        }

        // Exchange halves via smem: lane hl<4 of each half publishes token hl's
        // 4 expert sums.
        if (hl < TOK_PER_WARP) {
#pragma unroll
            for (int e = 0; e < EXP_HALF; e++)
                sLog[warp][hl][eBase + e] = acc[hl][e];
        }
        __syncwarp();

        // Lanes 0..3 each finish one token: bias + softmax + top-2.
        if (lane < TOK_PER_WARP) {
            const int token = tok0 + lane;
            if (token < ntok) {
                float logits[NEXP];
                float m = -INFINITY;
#pragma unroll
                for (int e = 0; e < NEXP; e++) {
                    logits[e] = sLog[warp][lane][e] + sB[e];
                    m = fmaxf(m, logits[e]);
                }
                float s = 0.0f;
                float ex[NEXP];
#pragma unroll
                for (int e = 0; e < NEXP; e++) {
                    ex[e] = __expf(logits[e] - m);
                    s += ex[e];
                }
                const float inv_s = 1.0f / s;

                // top-2 by logit (softmax monotonic); strict > keeps lowest
                // index on ties, matching jax.lax.top_k.
                int i0 = 0;
#pragma unroll
                for (int e = 1; e < NEXP; e++)
                    if (logits[e] > logits[i0]) i0 = e;
                int i1 = (i0 == 0) ? 1 : 0;
#pragma unroll
                for (int e = 0; e < NEXP; e++)
                    if (e != i0 && logits[e] > logits[i1]) i1 = e;

                // Output: [gates (ntok*2 f32)] ++ [indices (ntok*2 as f32)]
                out[token * 2 + 0] = ex[i0] * inv_s;
                out[token * 2 + 1] = ex[i1] * inv_s;
                if (write_idx) {
                    float* oi = out + (size_t)ntok * 2;
                    oi[token * 2 + 0] = (float)i0;
                    oi[token * 2 + 1] = (float)i1;
                }
            }
        }
        __syncwarp();
    }
}

extern "C" void kernel_launch(void* const* d_in, const int* in_sizes, int n_in,
                              void* d_out, int out_size) {
    const float* x = (const float*)d_in[0];
    const float* W = (const float*)d_in[1];
    const float* b = (const float*)d_in[2];
    float* out = (float*)d_out;

    const int ntok = in_sizes[0] / DIM;                 // 128*197 = 25216
    const int write_idx = (out_size >= 4 * ntok) ? 1 : 0;

    const int ntiles = (ntok + TOK_PER_BLOCK - 1) / TOK_PER_BLOCK;
    const int grid = (ntiles < NBLOCKS) ? ntiles : NBLOCKS;
    router_kernel<<<grid, THREADS>>>(x, W, b, out, ntok, write_idx);
}